// round 16
// baseline (speedup 1.0000x reference)
#include <cuda_runtime.h>
#include <cuda_fp16.h>
#include <math.h>
#include <stdint.h>

// Problem constants
#define BATCH 2
#define SQ    2048
#define DM    2048     // model dim
#define KVD   512      // G*HD
#define NH    32       // heads
#define NG    8        // kv groups
#define HDIM  64       // head dim

// Scratch (allocation-free rule: __device__ globals), all fp16
__device__ __half g_Qh[(size_t)BATCH * SQ * DM];   // Q, pre-scaled by 0.125
__device__ __half g_Kh[(size_t)BATCH * SQ * KVD];
__device__ __half g_Vh[(size_t)BATCH * SQ * KVD];  // TRANSPOSED: [b][g][d][s]
__device__ __half g_Ch[(size_t)BATCH * SQ * DM];   // ctx
__device__ __half g_Xh[(size_t)BATCH * SQ * DM];   // x
// packed fp16 weights: Wq | Wk | Wv | Wo
#define WQ_OFF 0
#define WK_OFF (2048 * 2048)
#define WV_OFF (WK_OFF + 512 * 2048)
#define WO_OFF (WV_OFF + 512 * 2048)
__device__ __half g_Wh[WO_OFF + 2048 * 2048];

// ---------------------------------------------------------------------------
// helpers
// ---------------------------------------------------------------------------
__device__ __forceinline__ uint32_t smem_u32(const void* p) {
    uint32_t a;
    asm("{ .reg .u64 t; cvta.to.shared.u64 t, %1; cvt.u32.u64 %0, t; }"
        : "=r"(a) : "l"(p));
    return a;
}
__device__ __forceinline__ void cp_async16(uint32_t dst, const void* src) {
    asm volatile("cp.async.cg.shared.global [%0], [%1], 16;" :: "r"(dst), "l"(src));
}
__device__ __forceinline__ void cp_commit() {
    asm volatile("cp.async.commit_group;" ::: "memory");
}
template <int N>
__device__ __forceinline__ void cp_wait() {
    asm volatile("cp.async.wait_group %0;" :: "n"(N) : "memory");
}
__device__ __forceinline__ void mma_f16(float* c, const uint32_t* a, const uint32_t* b) {
    asm volatile(
        "mma.sync.aligned.m16n8k16.row.col.f32.f16.f16.f32 "
        "{%0,%1,%2,%3}, {%4,%5,%6,%7}, {%8,%9}, {%0,%1,%2,%3};"
        : "+f"(c[0]), "+f"(c[1]), "+f"(c[2]), "+f"(c[3])
        : "r"(a[0]), "r"(a[1]), "r"(a[2]), "r"(a[3]), "r"(b[0]), "r"(b[1]));
}
__device__ __forceinline__ void ldsm_x4(uint32_t* r, uint32_t addr) {
    asm volatile("ldmatrix.sync.aligned.m8n8.x4.shared.b16 {%0,%1,%2,%3}, [%4];"
                 : "=r"(r[0]), "=r"(r[1]), "=r"(r[2]), "=r"(r[3]) : "r"(addr));
}
__device__ __forceinline__ uint32_t packh2(float lo, float hi) {
    __half2 h = __floats2half2_rn(lo, hi);
    return *(uint32_t*)&h;
}

// ---------------------------------------------------------------------------
// Fused one-shot fp32 -> fp16 conversion for x + all four weights.
// ---------------------------------------------------------------------------
#define N4_X ((BATCH * SQ * DM) / 4)     // 2097152
#define N4_Q ((DM * DM) / 4)             // 1048576
#define N4_K ((KVD * DM) / 4)            // 262144
#define N4_TOTAL (N4_X + 2 * N4_Q + 2 * N4_K)

__global__ __launch_bounds__(256) void cvt_all(
    const float4* __restrict__ x,  const float4* __restrict__ wq,
    const float4* __restrict__ wk, const float4* __restrict__ wv,
    const float4* __restrict__ wo, __half2* __restrict__ xh,
    __half2* __restrict__ wh)
{
    int i = blockIdx.x * 256 + threadIdx.x;
    if (i >= N4_TOTAL) return;
    const float4* s;
    __half2* d;
    if (i < N4_X) { s = x + i; d = xh + i * 2; }
    else {
        int j = i - N4_X;
        d = wh + j * 2;
        if (j < N4_Q)                   s = wq + j;
        else if (j < N4_Q + N4_K)       s = wk + (j - N4_Q);
        else if (j < N4_Q + 2 * N4_K)   s = wv + (j - N4_Q - N4_K);
        else                            s = wo + (j - N4_Q - 2 * N4_K);
    }
    float4 v = *s;
    d[0] = __floats2half2_rn(v.x, v.y);
    d[1] = __floats2half2_rn(v.z, v.w);
}

// ---------------------------------------------------------------------------
// FP16 mma.sync GEMM:  C[M,N] = A[M,K] . W[N,K]^T   (fp32 accumulate)
// CTA: 128x128 tile, BK=64 halves, 256 threads (8 warps, 2m x 4n; warp 64x32).
// 3-stage cp.async, ONE __syncthreads per k-tile; prefetch after ks=0 MMAs.
// csel 4 = fused QKV (Q scaled 0.125, V transposed); csel 3 = fp32 out.
// ---------------------------------------------------------------------------
#define HSTRIDE 72                            // halves per smem row (64 + pad)
#define STG_B (2 * 128 * HSTRIDE * 2)         // bytes per stage (A+B) = 36864
#define GEMM_SMEM (3 * STG_B)                 // 110592 bytes

__global__ __launch_bounds__(256, 2) void gemm_f16(
    int asel, int woff, int csel, float* __restrict__ Cext, int M, int K)
{
    extern __shared__ char smc[];
    const uint32_t sb = smem_u32(smc);
    const __half* A = asel ? g_Ch : g_Xh;
    const __half* W = g_Wh + woff;

    const int tid = threadIdx.x;
    const int wid = tid >> 5;
    const int lane = tid & 31;
    const int m0 = blockIdx.y * 128;
    const int n0 = blockIdx.x * 128;
    const int wm0 = (wid >> 2) * 64;
    const int wn0 = (wid & 3) * 32;

    // output routing
    __half* Ch = nullptr;
    int ldc = DM, cbase = n0;
    bool vtrans = false;
    float oscale = 1.f;
    if (csel == 4) {
        if (n0 < 2048)      { Ch = g_Qh; ldc = DM;  cbase = n0; oscale = 0.125f; }
        else if (n0 < 2560) { Ch = g_Kh; ldc = KVD; cbase = n0 - 2048; }
        else                { vtrans = true; cbase = n0 - 2560; }
    }

    // ldmatrix lane roles
    const int lt = lane & 7;
    const int tt = lane >> 3;
    const int arow = wm0 + lt + (tt & 1) * 8;
    const int acol = (tt >> 1) * 8;          // halves
    const int brow = wn0 + lt + (tt >> 1) * 8;
    const int bcol = (tt & 1) * 8;           // halves

    float c[4][4][4];
#pragma unroll
    for (int mt = 0; mt < 4; mt++)
#pragma unroll
        for (int nt = 0; nt < 4; nt++)
#pragma unroll
            for (int i = 0; i < 4; i++) c[mt][nt][i] = 0.f;

    const int nk = K / 64;

    auto issue = [&](int kt, int buf) {
        const uint32_t abase = sb + buf * STG_B;
        const uint32_t bbase = abase + 128 * HSTRIDE * 2;
        const int k0 = kt * 64;
#pragma unroll
        for (int i = 0; i < 4; i++) {
            int idx = tid + i * 256;           // 0..1023
            int row = idx >> 3;
            int ch = idx & 7;                  // 16B chunk = 8 halves
            cp_async16(abase + (row * HSTRIDE + ch * 8) * 2,
                       &A[(size_t)(m0 + row) * K + k0 + ch * 8]);
            cp_async16(bbase + (row * HSTRIDE + ch * 8) * 2,
                       &W[(size_t)(n0 + row) * K + k0 + ch * 8]);
        }
        cp_commit();
    };

    issue(0, 0);
    issue(1, 1);

    int buf = 0, wbuf = 2;
    for (int kt = 0; kt < nk; kt++) {
        cp_wait<1>();
        __syncthreads();

        const uint32_t stg = sb + buf * STG_B;
        const uint32_t a_base = stg + (arow * HSTRIDE + acol) * 2;
        const uint32_t b_base = stg + 128 * HSTRIDE * 2 + (brow * HSTRIDE + bcol) * 2;

#pragma unroll
        for (int ks = 0; ks < 4; ks++) {       // 4 x k16 = 64
            uint32_t a[4][4], b[2][4];
#pragma unroll
            for (int mt = 0; mt < 4; mt++)
                ldsm_x4(a[mt], a_base + (mt * 16 * HSTRIDE + ks * 16) * 2);
#pragma unroll
            for (int np = 0; np < 2; np++)
                ldsm_x4(b[np], b_base + (np * 16 * HSTRIDE + ks * 16) * 2);
#pragma unroll
            for (int mt = 0; mt < 4; mt++)
#pragma unroll
                for (int nt = 0; nt < 4; nt++)
                    mma_f16(c[mt][nt], a[mt], &b[nt >> 1][(nt & 1) * 2]);

            if (ks == 0) {
                if (kt + 2 < nk) issue(kt + 2, wbuf);
                else cp_commit();
            }
        }
        buf = (buf == 2) ? 0 : buf + 1;
        wbuf = (wbuf == 2) ? 0 : wbuf + 1;
    }

#pragma unroll
    for (int mt = 0; mt < 4; mt++) {
        const int r0 = m0 + wm0 + mt * 16 + (lane >> 2);
#pragma unroll
        for (int nt = 0; nt < 4; nt++) {
            const int col = cbase + wn0 + nt * 8 + (lane & 3) * 2;
            float v0 = c[mt][nt][0], v1 = c[mt][nt][1];
            float v2 = c[mt][nt][2], v3 = c[mt][nt][3];
            if (csel == 3) {
                *(float2*)&Cext[(size_t)r0 * DM + col] = make_float2(v0, v1);
                *(float2*)&Cext[(size_t)(r0 + 8) * DM + col] = make_float2(v2, v3);
            } else if (vtrans) {
                // V^T: g_Vh[((b*NG+g)*HDIM + d) * SQ + s]
                const int bb = r0 >> 11, s = r0 & 2047;
                const int gg = col >> 6, d = col & 63;
                __half* base = g_Vh + ((size_t)(bb * NG + gg) * HDIM + d) * SQ + s;
                base[0]      = __float2half_rn(v0);
                base[SQ]     = __float2half_rn(v1);
                base[8]      = __float2half_rn(v2);
                base[SQ + 8] = __float2half_rn(v3);
            } else {
                *(__half2*)&Ch[(size_t)r0 * ldc + col] =
                    __floats2half2_rn(v0 * oscale, v1 * oscale);
                *(__half2*)&Ch[(size_t)(r0 + 8) * ldc + col] =
                    __floats2half2_rn(v2 * oscale, v3 * oscale);
            }
        }
    }
}

// ---------------------------------------------------------------------------
// FP16 tensor-core causal GQA flash attention (fp32 softmax/accum).
// CTA: (qt, b*32+h); 256 threads = 8 warps; BQ=128 (16 q-rows/warp), BKV=64.
// 3-stage K/V cp.async pipeline (2 tiles in flight), register-direct P,
// all fragments via ldmatrix. One barrier per kv-tile.
// ---------------------------------------------------------------------------
#define TPAD  72                              // halves per row
#define KBUF_B (64 * TPAD * 2)                // 9216 bytes per K or V buffer
#define ATTN_SMEM (6 * KBUF_B + 128 * TPAD * 2)   // 73728 bytes

__global__ __launch_bounds__(256, 2) void gqa_attn_tc()
{
    extern __shared__ char smc[];
    const uint32_t sb = smem_u32(smc);
    const uint32_t sbK = sb;                  // 3 K buffers
    const uint32_t sbV = sb + 3 * KBUF_B;     // 3 V buffers
    const uint32_t sbP = sb + 6 * KBUF_B;     // Q staging (read-only after init)

    const int tid = threadIdx.x;
    const int w = tid >> 5;
    const int lane = tid & 31;
    const int r = lane >> 2;
    const int cb = lane & 3;
    const int qt = (int)gridDim.x - 1 - (int)blockIdx.x;   // heavy tiles first
    const int bh = blockIdx.y;
    const int b = bh >> 5, h = bh & 31, g = h >> 2;
    const int q0 = qt * 128;
    const int wrow = w * 16;

    // ldmatrix lane roles (A-pattern for Q, B-pattern for K/V)
    const int lt = lane & 7;
    const int tt = lane >> 3;
    const int parow = wrow + lt + (tt & 1) * 8;
    const int pacol = (tt >> 1) * 8;          // halves
    const int nbrow = lt + (tt >> 1) * 8;     // B-frag n row (kv for K, d for V)
    const int nbcol = (tt & 1) * 8;           // B-frag k col (halves)

    const __half* Qb = g_Qh + (size_t)b * SQ * DM + h * HDIM;
    const __half* Kb = g_Kh + (size_t)b * SQ * KVD + g * HDIM;
    const __half* Vb = g_Vh + (size_t)(b * NG + g) * HDIM * SQ;   // [d][s]

    const int nkt = qt * 2 + 2;

    auto issue_tile = [&](int kt) {
        const int buf = kt % 3;
        const uint32_t kbuf = sbK + buf * KBUF_B;
        const uint32_t vbuf = sbV + buf * KBUF_B;
        const int k0 = kt * 64;
#pragma unroll
        for (int i = 0; i < 2; i++) {
            int idx = tid + i * 256;           // 64 rows x 8 chunks
            int row = idx >> 3, ch = idx & 7;
            cp_async16(kbuf + (row * TPAD + ch * 8) * 2,
                       &Kb[(size_t)(k0 + row) * KVD + ch * 8]);
            cp_async16(vbuf + (row * TPAD + ch * 8) * 2,
                       &Vb[(size_t)row * SQ + k0 + ch * 8]);
        }
        cp_commit();
    };

    // Prologue: tile0, Q, tile1 all in flight
    issue_tile(0);
#pragma unroll
    for (int i = 0; i < 4; i++) {
        int idx = tid + i * 256;               // 128 rows x 8 chunks
        int row = idx >> 3, ch = idx & 7;
        cp_async16(sbP + (row * TPAD + ch * 8) * 2,
                   &Qb[(size_t)(q0 + row) * DM + ch * 8]);
    }
    cp_commit();
    if (nkt > 1) { issue_tile(1); cp_wait<1>(); }
    else cp_wait<0>();
    __syncthreads();                           // tile0 + Q published

    const uint32_t pA = sbP + (parow * TPAD + pacol) * 2;
    uint32_t qf[4][4];
#pragma unroll
    for (int ks = 0; ks < 4; ks++)
        ldsm_x4(qf[ks], pA + ks * 16 * 2);
    // (no barrier: sbP is never rewritten)

    float of[8][4];
#pragma unroll
    for (int dt = 0; dt < 8; dt++)
#pragma unroll
        for (int i = 0; i < 4; i++) of[dt][i] = 0.f;
    float m0r = -1e30f, m1r = -1e30f, l0 = 0.f, l1 = 0.f;

    for (int kt = 0; kt < nkt; kt++) {
        if (kt > 0) {
            if (kt + 1 < nkt) cp_wait<1>();    // tile kt done, kt+1 streaming
            else cp_wait<0>();
            __syncthreads();                   // publish kt; reads of kt-1 done
        }

        const int bsel = kt % 3;
        const uint32_t kBufA = sbK + bsel * KBUF_B + (nbrow * TPAD + nbcol) * 2;
        const uint32_t vBufA = sbV + bsel * KBUF_B + (nbrow * TPAD + nbcol) * 2;
        const int k0 = kt * 64;

        const bool active = (k0 <= q0 + wrow + 15);
        float sf[8][4];
        if (active) {
#pragma unroll
            for (int nt = 0; nt < 8; nt++)
#pragma unroll
                for (int i = 0; i < 4; i++) sf[nt][i] = 0.f;
#pragma unroll
            for (int ks = 0; ks < 4; ks++) {   // k16 over d=64
                uint32_t bf[4][4];
#pragma unroll
                for (int np = 0; np < 4; np++)
                    ldsm_x4(bf[np], kBufA + (np * 16 * TPAD + ks * 16) * 2);
#pragma unroll
                for (int nt = 0; nt < 8; nt++)
                    mma_f16(sf[nt], qf[ks], &bf[nt >> 1][(nt & 1) * 2]);
            }
        }

        if (kt + 2 < nkt) issue_tile(kt + 2);  // prefetch 2 ahead

        if (active) {
            if (k0 + 63 > q0 + wrow) {
                const int qr0 = q0 + wrow + r;
                const int qr1 = qr0 + 8;
#pragma unroll
                for (int nt = 0; nt < 8; nt++) {
                    const int kvc = k0 + nt * 8 + cb * 2;
                    if (kvc > qr0)     sf[nt][0] = -1e30f;
                    if (kvc + 1 > qr0) sf[nt][1] = -1e30f;
                    if (kvc > qr1)     sf[nt][2] = -1e30f;
                    if (kvc + 1 > qr1) sf[nt][3] = -1e30f;
                }
            }
            float mx0 = m0r, mx1 = m1r;
#pragma unroll
            for (int nt = 0; nt < 8; nt++) {
                mx0 = fmaxf(mx0, fmaxf(sf[nt][0], sf[nt][1]));
                mx1 = fmaxf(mx1, fmaxf(sf[nt][2], sf[nt][3]));
            }
            mx0 = fmaxf(mx0, __shfl_xor_sync(0xffffffffu, mx0, 1));
            mx0 = fmaxf(mx0, __shfl_xor_sync(0xffffffffu, mx0, 2));
            mx1 = fmaxf(mx1, __shfl_xor_sync(0xffffffffu, mx1, 1));
            mx1 = fmaxf(mx1, __shfl_xor_sync(0xffffffffu, mx1, 2));
            const float a0 = __expf(m0r - mx0), a1 = __expf(m1r - mx1);
            m0r = mx0; m1r = mx1;
            float s0 = 0.f, s1 = 0.f;
            // exp + in-register C->A fragment conversion (half2 packs)
            uint32_t pf[4][4];
#pragma unroll
            for (int nt = 0; nt < 8; nt++) {
                float p00 = __expf(sf[nt][0] - mx0);
                float p01 = __expf(sf[nt][1] - mx0);
                float p10 = __expf(sf[nt][2] - mx1);
                float p11 = __expf(sf[nt][3] - mx1);
                s0 += p00 + p01; s1 += p10 + p11;
                pf[nt >> 1][(nt & 1) * 2 + 0] = packh2(p00, p01);
                pf[nt >> 1][(nt & 1) * 2 + 1] = packh2(p10, p11);
            }
            s0 += __shfl_xor_sync(0xffffffffu, s0, 1);
            s0 += __shfl_xor_sync(0xffffffffu, s0, 2);
            s1 += __shfl_xor_sync(0xffffffffu, s1, 1);
            s1 += __shfl_xor_sync(0xffffffffu, s1, 2);
            l0 = l0 * a0 + s0;
            l1 = l1 * a1 + s1;
#pragma unroll
            for (int dt = 0; dt < 8; dt++) {
                of[dt][0] *= a0; of[dt][1] *= a0;
                of[dt][2] *= a1; of[dt][3] *= a1;
            }
            // O += P.V  (A = pf registers, B = V^T frags via ldmatrix)
#pragma unroll
            for (int ks = 0; ks < 4; ks++) {   // k16 over kv=64
                uint32_t vf[4][4];
#pragma unroll
                for (int np = 0; np < 4; np++)
                    ldsm_x4(vf[np], vBufA + (np * 16 * TPAD + ks * 16) * 2);
#pragma unroll
                for (int dt = 0; dt < 8; dt++)
                    mma_f16(of[dt], pf[ks], &vf[dt >> 1][(dt & 1) * 2]);
            }
        }
    }

    // epilogue: ctx (fp16) for the final GEMM
    const float i0 = 1.f / l0, i1 = 1.f / l1;
    __half* C0 = g_Ch + ((size_t)b * SQ + q0 + wrow + r) * DM + h * HDIM;
    __half* C1 = C0 + 8 * DM;
#pragma unroll
    for (int dt = 0; dt < 8; dt++) {
        const int col = dt * 8 + cb * 2;
        *(__half2*)&C0[col] = __floats2half2_rn(of[dt][0] * i0, of[dt][1] * i0);
        *(__half2*)&C1[col] = __floats2half2_rn(of[dt][2] * i1, of[dt][3] * i1);
    }
}

// ---------------------------------------------------------------------------
extern "C" void kernel_launch(void* const* d_in, const int* in_sizes, int n_in,
                              void* d_out, int out_size)
{
    (void)in_sizes; (void)n_in; (void)out_size;
    const float* x  = (const float*)d_in[0];
    const float* Wq = (const float*)d_in[1];
    const float* Wk = (const float*)d_in[2];
    const float* Wv = (const float*)d_in[3];
    const float* Wo = (const float*)d_in[4];
    float* out = (float*)d_out;

    const int M = BATCH * SQ;   // 4096

    cudaFuncSetAttribute(gemm_f16, cudaFuncAttributeMaxDynamicSharedMemorySize, GEMM_SMEM);
    cudaFuncSetAttribute(gqa_attn_tc, cudaFuncAttributeMaxDynamicSharedMemorySize, ATTN_SMEM);

    __half* xh; cudaGetSymbolAddress((void**)&xh, g_Xh);
    __half* wh; cudaGetSymbolAddress((void**)&wh, g_Wh);

    // Pre-convert x and all weights to fp16 in ONE launch
    cvt_all<<<(N4_TOTAL + 255) / 256, 256>>>(
        (const float4*)x, (const float4*)Wq, (const float4*)Wk,
        (const float4*)Wv, (const float4*)Wo, (__half2*)xh, (__half2*)wh);

    // Fused Q|K|V = x @ [Wq;Wk;Wv]^T  (Q scaled 0.125, V transposed)
    gemm_f16<<<dim3(3072 / 128, M / 128), 256, GEMM_SMEM>>>(0, 0, 4, nullptr, M, DM);
    // Causal GQA attention -> g_Ch
    gqa_attn_tc<<<dim3(SQ / 128, BATCH * NH), 256, ATTN_SMEM>>>();
    // out = ctx @ Wo^T  (fp32 output)
    gemm_f16<<<dim3(DM / 128, M / 128), 256, GEMM_SMEM>>>(1, WO_OFF, 3, out, M, DM);
}

// round 17
// speedup vs baseline: 1.0730x; 1.0730x over previous
#include <cuda_runtime.h>
#include <cuda_fp16.h>
#include <math.h>
#include <stdint.h>

// Problem constants
#define BATCH 2
#define SQ    2048
#define DM    2048     // model dim
#define KVD   512      // G*HD
#define NH    32       // heads
#define NG    8        // kv groups
#define HDIM  64       // head dim

// Scratch (allocation-free rule: __device__ globals), all fp16
__device__ __half g_Qh[(size_t)BATCH * SQ * DM];   // Q, pre-scaled by 0.125
__device__ __half g_Kh[(size_t)BATCH * SQ * KVD];
__device__ __half g_Vh[(size_t)BATCH * SQ * KVD];  // TRANSPOSED: [b][g][d][s]
__device__ __half g_Ch[(size_t)BATCH * SQ * DM];   // ctx
__device__ __half g_Xh[(size_t)BATCH * SQ * DM];   // x
// packed fp16 weights: Wq | Wk | Wv | Wo
#define WQ_OFF 0
#define WK_OFF (2048 * 2048)
#define WV_OFF (WK_OFF + 512 * 2048)
#define WO_OFF (WV_OFF + 512 * 2048)
__device__ __half g_Wh[WO_OFF + 2048 * 2048];

// ---------------------------------------------------------------------------
// helpers
// ---------------------------------------------------------------------------
__device__ __forceinline__ uint32_t smem_u32(const void* p) {
    uint32_t a;
    asm("{ .reg .u64 t; cvta.to.shared.u64 t, %1; cvt.u32.u64 %0, t; }"
        : "=r"(a) : "l"(p));
    return a;
}
__device__ __forceinline__ void cp_async16(uint32_t dst, const void* src) {
    asm volatile("cp.async.cg.shared.global [%0], [%1], 16;" :: "r"(dst), "l"(src));
}
__device__ __forceinline__ void cp_commit() {
    asm volatile("cp.async.commit_group;" ::: "memory");
}
template <int N>
__device__ __forceinline__ void cp_wait() {
    asm volatile("cp.async.wait_group %0;" :: "n"(N) : "memory");
}
__device__ __forceinline__ void mma_f16(float* c, const uint32_t* a, const uint32_t* b) {
    asm volatile(
        "mma.sync.aligned.m16n8k16.row.col.f32.f16.f16.f32 "
        "{%0,%1,%2,%3}, {%4,%5,%6,%7}, {%8,%9}, {%0,%1,%2,%3};"
        : "+f"(c[0]), "+f"(c[1]), "+f"(c[2]), "+f"(c[3])
        : "r"(a[0]), "r"(a[1]), "r"(a[2]), "r"(a[3]), "r"(b[0]), "r"(b[1]));
}
__device__ __forceinline__ void ldsm_x4(uint32_t* r, uint32_t addr) {
    asm volatile("ldmatrix.sync.aligned.m8n8.x4.shared.b16 {%0,%1,%2,%3}, [%4];"
                 : "=r"(r[0]), "=r"(r[1]), "=r"(r[2]), "=r"(r[3]) : "r"(addr));
}
__device__ __forceinline__ uint32_t packh2(float lo, float hi) {
    __half2 h = __floats2half2_rn(lo, hi);
    return *(uint32_t*)&h;
}
__device__ __forceinline__ uint32_t ex2h2(uint32_t x) {
    uint32_t r;
    asm("ex2.approx.f16x2 %0, %1;" : "=r"(r) : "r"(x));
    return r;
}
#define LOG2E 1.4426950408889634f

// ---------------------------------------------------------------------------
// Fused one-shot fp32 -> fp16 conversion for x + all four weights.
// ---------------------------------------------------------------------------
#define N4_X ((BATCH * SQ * DM) / 4)     // 2097152
#define N4_Q ((DM * DM) / 4)             // 1048576
#define N4_K ((KVD * DM) / 4)            // 262144
#define N4_TOTAL (N4_X + 2 * N4_Q + 2 * N4_K)

__global__ __launch_bounds__(256) void cvt_all(
    const float4* __restrict__ x,  const float4* __restrict__ wq,
    const float4* __restrict__ wk, const float4* __restrict__ wv,
    const float4* __restrict__ wo, __half2* __restrict__ xh,
    __half2* __restrict__ wh)
{
    int i = blockIdx.x * 256 + threadIdx.x;
    if (i >= N4_TOTAL) return;
    const float4* s;
    __half2* d;
    if (i < N4_X) { s = x + i; d = xh + i * 2; }
    else {
        int j = i - N4_X;
        d = wh + j * 2;
        if (j < N4_Q)                   s = wq + j;
        else if (j < N4_Q + N4_K)       s = wk + (j - N4_Q);
        else if (j < N4_Q + 2 * N4_K)   s = wv + (j - N4_Q - N4_K);
        else                            s = wo + (j - N4_Q - 2 * N4_K);
    }
    float4 v = *s;
    d[0] = __floats2half2_rn(v.x, v.y);
    d[1] = __floats2half2_rn(v.z, v.w);
}

// ---------------------------------------------------------------------------
// FP16 mma.sync GEMM:  C[M,N] = A[M,K] . W[N,K]^T   (fp32 accumulate)
// CTA: 128x128 tile, BK=64 halves, 256 threads (8 warps, 2m x 4n; warp 64x32).
// 3-stage cp.async, ONE __syncthreads per k-tile; prefetch after ks=0 MMAs.
// csel 4 = fused QKV (Q scaled 0.125, V transposed); csel 3 = fp32 out.
// ---------------------------------------------------------------------------
#define HSTRIDE 72                            // halves per smem row (64 + pad)
#define STG_B (2 * 128 * HSTRIDE * 2)         // bytes per stage (A+B) = 36864
#define GEMM_SMEM (3 * STG_B)                 // 110592 bytes

__global__ __launch_bounds__(256, 2) void gemm_f16(
    int asel, int woff, int csel, float* __restrict__ Cext, int M, int K)
{
    extern __shared__ char smc[];
    const uint32_t sb = smem_u32(smc);
    const __half* A = asel ? g_Ch : g_Xh;
    const __half* W = g_Wh + woff;

    const int tid = threadIdx.x;
    const int wid = tid >> 5;
    const int lane = tid & 31;
    const int m0 = blockIdx.y * 128;
    const int n0 = blockIdx.x * 128;
    const int wm0 = (wid >> 2) * 64;
    const int wn0 = (wid & 3) * 32;

    // output routing
    __half* Ch = nullptr;
    int ldc = DM, cbase = n0;
    bool vtrans = false;
    float oscale = 1.f;
    if (csel == 4) {
        if (n0 < 2048)      { Ch = g_Qh; ldc = DM;  cbase = n0; oscale = 0.125f; }
        else if (n0 < 2560) { Ch = g_Kh; ldc = KVD; cbase = n0 - 2048; }
        else                { vtrans = true; cbase = n0 - 2560; }
    }

    // ldmatrix lane roles
    const int lt = lane & 7;
    const int tt = lane >> 3;
    const int arow = wm0 + lt + (tt & 1) * 8;
    const int acol = (tt >> 1) * 8;          // halves
    const int brow = wn0 + lt + (tt >> 1) * 8;
    const int bcol = (tt & 1) * 8;           // halves

    float c[4][4][4];
#pragma unroll
    for (int mt = 0; mt < 4; mt++)
#pragma unroll
        for (int nt = 0; nt < 4; nt++)
#pragma unroll
            for (int i = 0; i < 4; i++) c[mt][nt][i] = 0.f;

    const int nk = K / 64;

    auto issue = [&](int kt, int buf) {
        const uint32_t abase = sb + buf * STG_B;
        const uint32_t bbase = abase + 128 * HSTRIDE * 2;
        const int k0 = kt * 64;
#pragma unroll
        for (int i = 0; i < 4; i++) {
            int idx = tid + i * 256;           // 0..1023
            int row = idx >> 3;
            int ch = idx & 7;                  // 16B chunk = 8 halves
            cp_async16(abase + (row * HSTRIDE + ch * 8) * 2,
                       &A[(size_t)(m0 + row) * K + k0 + ch * 8]);
            cp_async16(bbase + (row * HSTRIDE + ch * 8) * 2,
                       &W[(size_t)(n0 + row) * K + k0 + ch * 8]);
        }
        cp_commit();
    };

    issue(0, 0);
    issue(1, 1);

    int buf = 0, wbuf = 2;
    for (int kt = 0; kt < nk; kt++) {
        cp_wait<1>();
        __syncthreads();

        const uint32_t stg = sb + buf * STG_B;
        const uint32_t a_base = stg + (arow * HSTRIDE + acol) * 2;
        const uint32_t b_base = stg + 128 * HSTRIDE * 2 + (brow * HSTRIDE + bcol) * 2;

#pragma unroll
        for (int ks = 0; ks < 4; ks++) {       // 4 x k16 = 64
            uint32_t a[4][4], b[2][4];
#pragma unroll
            for (int mt = 0; mt < 4; mt++)
                ldsm_x4(a[mt], a_base + (mt * 16 * HSTRIDE + ks * 16) * 2);
#pragma unroll
            for (int np = 0; np < 2; np++)
                ldsm_x4(b[np], b_base + (np * 16 * HSTRIDE + ks * 16) * 2);
#pragma unroll
            for (int mt = 0; mt < 4; mt++)
#pragma unroll
                for (int nt = 0; nt < 4; nt++)
                    mma_f16(c[mt][nt], a[mt], &b[nt >> 1][(nt & 1) * 2]);

            if (ks == 0) {
                if (kt + 2 < nk) issue(kt + 2, wbuf);
                else cp_commit();
            }
        }
        buf = (buf == 2) ? 0 : buf + 1;
        wbuf = (wbuf == 2) ? 0 : wbuf + 1;
    }

#pragma unroll
    for (int mt = 0; mt < 4; mt++) {
        const int r0 = m0 + wm0 + mt * 16 + (lane >> 2);
#pragma unroll
        for (int nt = 0; nt < 4; nt++) {
            const int col = cbase + wn0 + nt * 8 + (lane & 3) * 2;
            float v0 = c[mt][nt][0], v1 = c[mt][nt][1];
            float v2 = c[mt][nt][2], v3 = c[mt][nt][3];
            if (csel == 3) {
                *(float2*)&Cext[(size_t)r0 * DM + col] = make_float2(v0, v1);
                *(float2*)&Cext[(size_t)(r0 + 8) * DM + col] = make_float2(v2, v3);
            } else if (vtrans) {
                // V^T: g_Vh[((b*NG+g)*HDIM + d) * SQ + s]
                const int bb = r0 >> 11, s = r0 & 2047;
                const int gg = col >> 6, d = col & 63;
                __half* base = g_Vh + ((size_t)(bb * NG + gg) * HDIM + d) * SQ + s;
                base[0]      = __float2half_rn(v0);
                base[SQ]     = __float2half_rn(v1);
                base[8]      = __float2half_rn(v2);
                base[SQ + 8] = __float2half_rn(v3);
            } else {
                *(__half2*)&Ch[(size_t)r0 * ldc + col] =
                    __floats2half2_rn(v0 * oscale, v1 * oscale);
                *(__half2*)&Ch[(size_t)(r0 + 8) * ldc + col] =
                    __floats2half2_rn(v2 * oscale, v3 * oscale);
            }
        }
    }
}

// ---------------------------------------------------------------------------
// FP16 tensor-core causal GQA flash attention (fp32 softmax stats/accum).
// CTA: (qt, b*32+h); 256 threads = 8 warps; BQ=128 (16 q-rows/warp), BKV=64.
// Register-direct P via ex2.approx.f16x2 (t = s*log2e - m*log2e in fp32 FMA,
// pack, one MUFU op per pair). Row sums l accumulated by an extra MMA against
// an all-ones B fragment (fp32 accumulator, alpha-rescaled like O).
// ---------------------------------------------------------------------------
#define TPAD  72                              // halves per row
#define KBUF_B (64 * TPAD * 2)                // 9216 bytes per K or V buffer
#define ATTN_SMEM (4 * KBUF_B + 128 * TPAD * 2)   // 55296 bytes

__global__ __launch_bounds__(256, 2) void gqa_attn_tc()
{
    extern __shared__ char smc[];
    const uint32_t sb = smem_u32(smc);
    const uint32_t sbK = sb;
    const uint32_t sbV = sb + 2 * KBUF_B;
    const uint32_t sbP = sb + 4 * KBUF_B;     // Q staging only

    const int tid = threadIdx.x;
    const int w = tid >> 5;
    const int lane = tid & 31;
    const int r = lane >> 2;
    const int cb = lane & 3;
    const int qt = (int)gridDim.x - 1 - (int)blockIdx.x;   // heavy tiles first
    const int bh = blockIdx.y;
    const int b = bh >> 5, h = bh & 31, g = h >> 2;
    const int q0 = qt * 128;
    const int wrow = w * 16;

    // ldmatrix lane roles (A-pattern for Q, B-pattern for K/V)
    const int lt = lane & 7;
    const int tt = lane >> 3;
    const int parow = wrow + lt + (tt & 1) * 8;
    const int pacol = (tt >> 1) * 8;          // halves
    const int nbrow = lt + (tt >> 1) * 8;     // B-frag n row (kv for K, d for V)
    const int nbcol = (tt & 1) * 8;           // B-frag k col (halves)

    const __half* Qb = g_Qh + (size_t)b * SQ * DM + h * HDIM;
    const __half* Kb = g_Kh + (size_t)b * SQ * KVD + g * HDIM;
    const __half* Vb = g_Vh + (size_t)(b * NG + g) * HDIM * SQ;   // [d][s]

    // Stage Q tile via cp.async (already scaled by 0.125)
#pragma unroll
    for (int i = 0; i < 4; i++) {
        int idx = tid + i * 256;               // 128 rows x 8 chunks
        int row = idx >> 3, ch = idx & 7;
        cp_async16(sbP + (row * TPAD + ch * 8) * 2,
                   &Qb[(size_t)(q0 + row) * DM + ch * 8]);
    }
    cp_commit();
    cp_wait<0>();
    __syncthreads();

    const uint32_t pA = sbP + (parow * TPAD + pacol) * 2;
    uint32_t qf[4][4];
#pragma unroll
    for (int ks = 0; ks < 4; ks++)
        ldsm_x4(qf[ks], pA + ks * 16 * 2);
    __syncthreads();

    float of[8][4];
#pragma unroll
    for (int dt = 0; dt < 8; dt++)
#pragma unroll
        for (int i = 0; i < 4; i++) of[dt][i] = 0.f;
    float ls[4] = {0.f, 0.f, 0.f, 0.f};        // row-sum accumulator (ones-MMA)
    float m0r = -1e30f, m1r = -1e30f;
    const uint32_t ONE2 = 0x3C003C00u;         // half2(1.0, 1.0)
    uint32_t onesb[2] = {ONE2, ONE2};

    const int nkt = qt * 2 + 2;

    auto issue_tile = [&](int kt) {
        const int buf = kt & 1;
        const uint32_t kbuf = sbK + buf * KBUF_B;
        const uint32_t vbuf = sbV + buf * KBUF_B;
        const int k0 = kt * 64;
#pragma unroll
        for (int i = 0; i < 2; i++) {
            int idx = tid + i * 256;           // 64 rows x 8 chunks
            int row = idx >> 3, ch = idx & 7;
            cp_async16(kbuf + (row * TPAD + ch * 8) * 2,
                       &Kb[(size_t)(k0 + row) * KVD + ch * 8]);
            cp_async16(vbuf + (row * TPAD + ch * 8) * 2,
                       &Vb[(size_t)row * SQ + k0 + ch * 8]);
        }
        cp_commit();
    };

    issue_tile(0);

    for (int kt = 0; kt < nkt; kt++) {
        cp_wait<0>();
        __syncthreads();

        const uint32_t kBufA = sbK + (kt & 1) * KBUF_B + (nbrow * TPAD + nbcol) * 2;
        const uint32_t vBufA = sbV + (kt & 1) * KBUF_B + (nbrow * TPAD + nbcol) * 2;
        const int k0 = kt * 64;

        const bool active = (k0 <= q0 + wrow + 15);
        float sf[8][4];
        if (active) {
#pragma unroll
            for (int nt = 0; nt < 8; nt++)
#pragma unroll
                for (int i = 0; i < 4; i++) sf[nt][i] = 0.f;
#pragma unroll
            for (int ks = 0; ks < 4; ks++) {   // k16 over d=64
                uint32_t bf[4][4];
#pragma unroll
                for (int np = 0; np < 4; np++)
                    ldsm_x4(bf[np], kBufA + (np * 16 * TPAD + ks * 16) * 2);
#pragma unroll
                for (int nt = 0; nt < 8; nt++)
                    mma_f16(sf[nt], qf[ks], &bf[nt >> 1][(nt & 1) * 2]);
            }
        }

        if (kt + 1 < nkt) issue_tile(kt + 1);

        if (active) {
            if (k0 + 63 > q0 + wrow) {
                const int qr0 = q0 + wrow + r;
                const int qr1 = qr0 + 8;
#pragma unroll
                for (int nt = 0; nt < 8; nt++) {
                    const int kvc = k0 + nt * 8 + cb * 2;
                    if (kvc > qr0)     sf[nt][0] = -1e30f;
                    if (kvc + 1 > qr0) sf[nt][1] = -1e30f;
                    if (kvc > qr1)     sf[nt][2] = -1e30f;
                    if (kvc + 1 > qr1) sf[nt][3] = -1e30f;
                }
            }
            float mx0 = m0r, mx1 = m1r;
#pragma unroll
            for (int nt = 0; nt < 8; nt++) {
                mx0 = fmaxf(mx0, fmaxf(sf[nt][0], sf[nt][1]));
                mx1 = fmaxf(mx1, fmaxf(sf[nt][2], sf[nt][3]));
            }
            mx0 = fmaxf(mx0, __shfl_xor_sync(0xffffffffu, mx0, 1));
            mx0 = fmaxf(mx0, __shfl_xor_sync(0xffffffffu, mx0, 2));
            mx1 = fmaxf(mx1, __shfl_xor_sync(0xffffffffu, mx1, 1));
            mx1 = fmaxf(mx1, __shfl_xor_sync(0xffffffffu, mx1, 2));
            const float a0 = __expf(m0r - mx0), a1 = __expf(m1r - mx1);
            m0r = mx0; m1r = mx1;
            const float mxl0 = mx0 * LOG2E, mxl1 = mx1 * LOG2E;
            // exp via ex2.approx.f16x2, result directly in PV A-fragment form
            uint32_t pf[4][4];
#pragma unroll
            for (int nt = 0; nt < 8; nt++) {
                float t00 = fmaf(sf[nt][0], LOG2E, -mxl0);
                float t01 = fmaf(sf[nt][1], LOG2E, -mxl0);
                float t10 = fmaf(sf[nt][2], LOG2E, -mxl1);
                float t11 = fmaf(sf[nt][3], LOG2E, -mxl1);
                pf[nt >> 1][(nt & 1) * 2 + 0] = ex2h2(packh2(t00, t01));
                pf[nt >> 1][(nt & 1) * 2 + 1] = ex2h2(packh2(t10, t11));
            }
            // rescale O and l accumulators
#pragma unroll
            for (int dt = 0; dt < 8; dt++) {
                of[dt][0] *= a0; of[dt][1] *= a0;
                of[dt][2] *= a1; of[dt][3] *= a1;
            }
            ls[0] *= a0; ls[1] *= a0; ls[2] *= a1; ls[3] *= a1;
            // O += P.V ; l += P.1  (B = V^T frags via ldmatrix, + ones frag)
#pragma unroll
            for (int ks = 0; ks < 4; ks++) {   // k16 over kv=64
                uint32_t vf[4][4];
#pragma unroll
                for (int np = 0; np < 4; np++)
                    ldsm_x4(vf[np], vBufA + (np * 16 * TPAD + ks * 16) * 2);
#pragma unroll
                for (int dt = 0; dt < 8; dt++)
                    mma_f16(of[dt], pf[ks], &vf[dt >> 1][(dt & 1) * 2]);
                mma_f16(ls, pf[ks], onesb);
            }
        }
    }

    // epilogue: ctx (fp16) for the final GEMM; l from ones-MMA accumulator
    const float i0 = 1.f / ls[0], i1 = 1.f / ls[2];
    __half* C0 = g_Ch + ((size_t)b * SQ + q0 + wrow + r) * DM + h * HDIM;
    __half* C1 = C0 + 8 * DM;
#pragma unroll
    for (int dt = 0; dt < 8; dt++) {
        const int col = dt * 8 + cb * 2;
        *(__half2*)&C0[col] = __floats2half2_rn(of[dt][0] * i0, of[dt][1] * i0);
        *(__half2*)&C1[col] = __floats2half2_rn(of[dt][2] * i1, of[dt][3] * i1);
    }
}

// ---------------------------------------------------------------------------
extern "C" void kernel_launch(void* const* d_in, const int* in_sizes, int n_in,
                              void* d_out, int out_size)
{
    (void)in_sizes; (void)n_in; (void)out_size;
    const float* x  = (const float*)d_in[0];
    const float* Wq = (const float*)d_in[1];
    const float* Wk = (const float*)d_in[2];
    const float* Wv = (const float*)d_in[3];
    const float* Wo = (const float*)d_in[4];
    float* out = (float*)d_out;

    const int M = BATCH * SQ;   // 4096

    cudaFuncSetAttribute(gemm_f16, cudaFuncAttributeMaxDynamicSharedMemorySize, GEMM_SMEM);
    cudaFuncSetAttribute(gqa_attn_tc, cudaFuncAttributeMaxDynamicSharedMemorySize, ATTN_SMEM);

    __half* xh; cudaGetSymbolAddress((void**)&xh, g_Xh);
    __half* wh; cudaGetSymbolAddress((void**)&wh, g_Wh);

    // Pre-convert x and all weights to fp16 in ONE launch
    cvt_all<<<(N4_TOTAL + 255) / 256, 256>>>(
        (const float4*)x, (const float4*)Wq, (const float4*)Wk,
        (const float4*)Wv, (const float4*)Wo, (__half2*)xh, (__half2*)wh);

    // Fused Q|K|V = x @ [Wq;Wk;Wv]^T  (Q scaled 0.125, V transposed)
    gemm_f16<<<dim3(3072 / 128, M / 128), 256, GEMM_SMEM>>>(0, 0, 4, nullptr, M, DM);
    // Causal GQA attention -> g_Ch
    gqa_attn_tc<<<dim3(SQ / 128, BATCH * NH), 256, ATTN_SMEM>>>();
    // out = ctx @ Wo^T  (fp32 output)
    gemm_f16<<<dim3(DM / 128, M / 128), 256, GEMM_SMEM>>>(1, WO_OFF, 3, out, M, DM);
}